// round 1
// baseline (speedup 1.0000x reference)
#include <cuda_runtime.h>
#include <math.h>

// Problem geometry (static, from reference):
// x, x_r: (1, 3, 32, 512, 512) float32
// patch: hc=wc=32 -> nh=nw=16 -> 256 patches/frame, 32 frames -> 8192 patches
// patch elems: 3 * 32 * 32 = 3072 ; P = mean(|x - x_r| * 0.5) over patch
// out = log( mean_t( max(0, max_patches P[t,:,:]) ) )

#define C_STRIDE   (32 * 512 * 512)   // channel stride in floats
#define T_STRIDE   (512 * 512)        // frame stride in floats
#define W          512
#define W4         (W / 4)            // row stride in float4
#define NPATCH     8192               // 32 * 16 * 16

__device__ float g_P[NPATCH];

// One CTA per patch. 256 threads, each handles 3 float4 per tensor (768 float4 = 3072 floats).
__global__ __launch_bounds__(256) void patch_sum_kernel(
    const float4* __restrict__ x, const float4* __restrict__ xr)
{
    const int p  = blockIdx.x;          // 0..8191
    const int t  = p >> 8;              // frame
    const int ph = (p >> 4) & 15;       // patch row
    const int pw = p & 15;              // patch col

    // base offset (in float4) of this patch for channel 0
    const int base4 = t * (T_STRIDE / 4) + (ph * 32) * W4 + pw * 8;

    float acc = 0.0f;
    #pragma unroll
    for (int k = 0; k < 3; k++) {
        const int f   = threadIdx.x + (k << 8);   // 0..767 float4-index within patch
        const int c   = f >> 8;                   // channel 0..2
        const int rem = f & 255;
        const int r   = rem >> 3;                 // row within patch 0..31
        const int c4  = rem & 7;                  // float4 within row 0..7
        const int idx = base4 + c * (C_STRIDE / 4) + r * W4 + c4;
        float4 a = x[idx];
        float4 b = xr[idx];
        acc += fabsf(a.x - b.x) + fabsf(a.y - b.y)
             + fabsf(a.z - b.z) + fabsf(a.w - b.w);
    }

    // block reduction: warp shuffle then 8-wide shared
    #pragma unroll
    for (int o = 16; o > 0; o >>= 1)
        acc += __shfl_down_sync(0xFFFFFFFFu, acc, o);

    __shared__ float s[8];
    if ((threadIdx.x & 31) == 0) s[threadIdx.x >> 5] = acc;
    __syncthreads();

    if (threadIdx.x < 8) {
        float v = s[threadIdx.x];
        #pragma unroll
        for (int o = 4; o > 0; o >>= 1)
            v += __shfl_down_sync(0xFFu, v, o);
        if (threadIdx.x == 0)
            g_P[p] = v * (0.5f / 3072.0f);   // |.|/2 then mean over 3072
    }
}

// Single CTA: per-frame max (clamped at 0), mean over 32 frames, log.
__global__ __launch_bounds__(256) void final_reduce_kernel(float* __restrict__ out)
{
    const int tid = threadIdx.x;
    const int t   = tid >> 3;   // frame 0..31
    const int j   = tid & 7;    // sub-slice 0..7

    float m = 0.0f;             // clamp-at-0 baked into init
    #pragma unroll
    for (int k = 0; k < 32; k++)
        m = fmaxf(m, g_P[t * 256 + j * 32 + k]);

    __shared__ float sm[256];
    sm[tid] = m;
    __syncthreads();

    __shared__ float tmax[32];
    if (j == 0) {
        float v = m;
        #pragma unroll
        for (int q = 1; q < 8; q++) v = fmaxf(v, sm[t * 8 + q]);
        tmax[t] = v;
    }
    __syncthreads();

    if (tid < 32) {
        float v = tmax[tid];
        #pragma unroll
        for (int o = 16; o > 0; o >>= 1)
            v += __shfl_down_sync(0xFFFFFFFFu, v, o);
        if (tid == 0)
            out[0] = logf(v * (1.0f / 32.0f));
    }
}

extern "C" void kernel_launch(void* const* d_in, const int* in_sizes, int n_in,
                              void* d_out, int out_size)
{
    const float4* x  = (const float4*)d_in[0];
    const float4* xr = (const float4*)d_in[1];
    float* out = (float*)d_out;

    patch_sum_kernel<<<NPATCH, 256>>>(x, xr);
    final_reduce_kernel<<<1, 256>>>(out);
}

// round 3
// speedup vs baseline: 1.1151x; 1.1151x over previous
#include <cuda_runtime.h>
#include <math.h>

// x, x_r: (1, 3, 32, 512, 512) float32
// patch: hc=wc=32 -> 16x16 patches/frame, 32 frames -> 8192 patches of 3*32*32=3072 elems
// P = mean(|x - x_r| * 0.5) per patch ; out = log( mean_t( max(0, max_p P) ) )

#define C_STRIDE   (32 * 512 * 512)
#define T_STRIDE   (512 * 512)
#define W4         (512 / 4)
#define NPATCH     8192
#define NFRAME     32

__device__ int          g_M[NFRAME];   // per-frame max as float-bits (all >= 0); zero-init = clamp(0)
__device__ unsigned int g_count;       // CTA completion counter (reset by last CTA)

__global__ __launch_bounds__(256) void patch_loss_fused(
    const float4* __restrict__ x, const float4* __restrict__ xr,
    float* __restrict__ out)
{
    const int p  = blockIdx.x;          // 0..8191
    const int t  = p >> 8;              // frame
    const int ph = (p >> 4) & 15;
    const int pw = p & 15;

    const int base4 = t * (T_STRIDE / 4) + (ph * 32) * W4 + pw * 8;

    float acc = 0.0f;
    #pragma unroll
    for (int k = 0; k < 3; k++) {
        const int f   = threadIdx.x + (k << 8);   // float4-index within patch 0..767
        const int c   = f >> 8;                   // channel
        const int rem = f & 255;
        const int r   = rem >> 3;                 // row in patch
        const int c4  = rem & 7;                  // float4 in row
        const int idx = base4 + c * (C_STRIDE / 4) + r * W4 + c4;
        float4 a = x[idx];
        float4 b = xr[idx];
        acc += fabsf(a.x - b.x) + fabsf(a.y - b.y)
             + fabsf(a.z - b.z) + fabsf(a.w - b.w);
    }

    // block sum: warp shuffle, then 8 warp-leaders
    #pragma unroll
    for (int o = 16; o > 0; o >>= 1)
        acc += __shfl_down_sync(0xFFFFFFFFu, acc, o);

    __shared__ float s[8];
    __shared__ bool  last;
    if ((threadIdx.x & 31) == 0) s[threadIdx.x >> 5] = acc;
    __syncthreads();

    if (threadIdx.x == 0) {
        float v = s[0];
        #pragma unroll
        for (int q = 1; q < 8; q++) v += s[q];
        const float P = v * (0.5f / 3072.0f);
        // per-frame max; float-as-int atomicMax valid since P >= 0
        atomicMax(&g_M[t], __float_as_int(P));
        __threadfence();   // make the max visible before signaling completion
        const unsigned int old = atomicAdd(&g_count, 1u);
        last = (old == NPATCH - 1);
    }
    __syncthreads();

    if (last) {
        __threadfence();   // order: observed all counts -> now read all maxima
        // this CTA is the final reducer: 32 frame maxima -> mean -> log
        if (threadIdx.x < 32) {
            const float m = __int_as_float(__ldcg(&g_M[threadIdx.x]));
            float v = m;
            #pragma unroll
            for (int o = 16; o > 0; o >>= 1)
                v += __shfl_down_sync(0xFFFFFFFFu, v, o);
            if (threadIdx.x == 0) {
                out[0] = logf(v * (1.0f / 32.0f));
                g_count = 0;              // reset for next graph replay
            }
            g_M[threadIdx.x] = 0;         // reset per-frame maxima
        }
    }
}

extern "C" void kernel_launch(void* const* d_in, const int* in_sizes, int n_in,
                              void* d_out, int out_size)
{
    const float4* x  = (const float4*)d_in[0];
    const float4* xr = (const float4*)d_in[1];
    patch_loss_fused<<<NPATCH, 256>>>(x, xr, (float*)d_out);
}